// round 1
// baseline (speedup 1.0000x reference)
#include <cuda_runtime.h>
#include <cuda_bf16.h>

#define D 128
#define N_MAX 50000

// Scratch: projected features h = X @ W^T  (25.6 MB, static device array per rules)
__device__ float g_h[(size_t)N_MAX * D];

// ---------------------------------------------------------------------------
// Kernel 1: h = X @ W^T   (X: [n,128], W: [128,128] row-major [out,in])
// Block: 256 threads, 32 rows per block.
// Shared: WT[128][129] (padded transpose of W, conflict-free store AND load)
//         xs [32][128]  (X tile, read back as float4 broadcasts)
// Thread (c = t&127, rg = t>>7) computes column c for 16 rows.
// ---------------------------------------------------------------------------
__global__ void gemm_xwt_kernel(const float* __restrict__ X,
                                const float* __restrict__ W,
                                int n) {
    extern __shared__ float sm[];
    float* WT = sm;                 // 128*129 floats
    float* xs = sm + 128 * 129;     // 32*128 floats
    float4* xs4 = (float4*)xs;

    const int t = threadIdx.x;
    const int R0 = blockIdx.x * 32;

    // Load + transpose W: WT[k*129 + j] = W[j*128 + k]
    // store banks: (k*129 + j) % 32 = (k + j) % 32, k consecutive across lanes -> conflict-free
    for (int idx = t; idx < D * D; idx += 256) {
        int j = idx >> 7;
        int k = idx & 127;
        WT[k * 129 + j] = W[idx];
    }

    // Load X tile (32 rows x 128) as float4, coalesced
    const float4* X4 = (const float4*)X;
    for (int idx = t; idx < 32 * 32; idx += 256) {
        int row = idx >> 5;
        int kk = idx & 31;
        float4 v = make_float4(0.f, 0.f, 0.f, 0.f);
        if (R0 + row < n) v = X4[(size_t)(R0 + row) * 32 + kk];
        xs4[idx] = v;
    }
    __syncthreads();

    const int c = t & 127;
    const int rg = t >> 7;  // 0 or 1

    float acc[16];
#pragma unroll
    for (int i = 0; i < 16; i++) acc[i] = 0.f;

#pragma unroll 2
    for (int k4 = 0; k4 < 32; ++k4) {
        const int kb = k4 * 4;
        // load banks: (k*129 + c) % 32 = (k + c) % 32, c consecutive -> conflict-free
        float w0 = WT[(kb + 0) * 129 + c];
        float w1 = WT[(kb + 1) * 129 + c];
        float w2 = WT[(kb + 2) * 129 + c];
        float w3 = WT[(kb + 3) * 129 + c];
#pragma unroll
        for (int i = 0; i < 16; i++) {
            float4 xv = xs4[(rg * 16 + i) * 32 + k4];  // broadcast within warp
            acc[i] = fmaf(xv.x, w0, acc[i]);
            acc[i] = fmaf(xv.y, w1, acc[i]);
            acc[i] = fmaf(xv.z, w2, acc[i]);
            acc[i] = fmaf(xv.w, w3, acc[i]);
        }
    }

#pragma unroll
    for (int i = 0; i < 16; i++) {
        int row = R0 + rg * 16 + i;
        if (row < n) g_h[(size_t)row * D + c] = acc[i];
    }
}

// ---------------------------------------------------------------------------
// Kernel 2: fused 3-graph SPMM with gate folded into edge value.
// Warp per edge: per lane 1x LDG.128 gather from g_h (L2-resident) and
// 1x red.global.add.v4.f32 scatter into out (L2-resident).
// ---------------------------------------------------------------------------
__global__ void spmm_kernel(const int* __restrict__ rows,
                            const int* __restrict__ cols,
                            const float* __restrict__ vals,
                            const float* __restrict__ alpha,
                            float* __restrict__ out,
                            int E, int GE) {
    // Gates: tiny, recompute per thread (3 L2-cached loads + MUFU)
    const float ga0 = 1.f / (1.f + __expf(-__ldg(alpha + 0)));
    const float ga1 = 1.f / (1.f + __expf(-__ldg(alpha + 1)));
    const float ga2 = 1.f / (1.f + __expf(-__ldg(alpha + 2)));

    const int lane = threadIdx.x & 31;
    const int warp = (blockIdx.x * blockDim.x + threadIdx.x) >> 5;
    const int nw = (gridDim.x * blockDim.x) >> 5;
    const float4* H4 = (const float4*)g_h;

    for (int e = warp; e < GE; e += nw) {
        int r = __ldg(rows + e);
        int c = __ldg(cols + e);
        float v = __ldg(vals + e);
        float gate = (e < E) ? ga0 : ((e < 2 * E) ? ga1 : ga2);
        v *= gate;

        float4 hv = H4[(size_t)c * 32 + lane];
        float mx = v * hv.x, my = v * hv.y, mz = v * hv.z, mw = v * hv.w;

        float* p = out + (size_t)r * D + lane * 4;
        asm volatile("red.global.add.v4.f32 [%0], {%1, %2, %3, %4};"
                     :: "l"(p), "f"(mx), "f"(my), "f"(mz), "f"(mw)
                     : "memory");
    }
}

// ---------------------------------------------------------------------------
extern "C" void kernel_launch(void* const* d_in, const int* in_sizes, int n_in,
                              void* d_out, int out_size) {
    const float* X     = (const float*)d_in[0];
    const float* W     = (const float*)d_in[1];
    const float* alpha = (const float*)d_in[2];
    const int*   rows  = (const int*)d_in[3];
    const int*   cols  = (const int*)d_in[4];
    const float* vals  = (const float*)d_in[5];
    float* out = (float*)d_out;

    const int n  = in_sizes[0] / D;      // 50000
    const int G  = in_sizes[2];          // 3
    const int GE = in_sizes[3];          // 2400000
    const int E  = GE / G;               // 800000

    // Output is poisoned; zero it (graph-capturable memset node)
    cudaMemsetAsync(d_out, 0, (size_t)out_size * sizeof(float), 0);

    const int smem = (128 * 129 + 32 * 128) * 4;  // 82432 B
    cudaFuncSetAttribute(gemm_xwt_kernel,
                         cudaFuncAttributeMaxDynamicSharedMemorySize, smem);
    gemm_xwt_kernel<<<(n + 31) / 32, 256, smem>>>(X, W, n);

    spmm_kernel<<<1184, 256>>>(rows, cols, vals, alpha, out, E, GE);
}

// round 2
// speedup vs baseline: 1.2338x; 1.2338x over previous
#include <cuda_runtime.h>
#include <cuda_fp16.h>

#define D 128
#define N_MAX 50000
#define E_MAX 2400000

// Scratch (static device arrays per harness rules)
__device__ __half g_h_half[(size_t)N_MAX * D];   // projected features, fp16 (12.8MB)
__device__ int2   g_cv[E_MAX];                   // CSR payload: (col, gate*val) (19.2MB)
__device__ int    g_count[N_MAX];
__device__ int    g_start[N_MAX + 1];
__device__ int    g_cursor[N_MAX];

// ---------------------------------------------------------------------------
// Kernel 1: h = X @ W^T  ->  g_h_half (fp32 accumulate, fp16 store)
// ---------------------------------------------------------------------------
__global__ void gemm_xwt_kernel(const float* __restrict__ X,
                                const float* __restrict__ W,
                                int n) {
    extern __shared__ float sm[];
    float* WT = sm;                 // 128*129 floats
    float* xs = sm + 128 * 129;     // 32*128 floats
    float4* xs4 = (float4*)xs;

    const int t = threadIdx.x;
    const int R0 = blockIdx.x * 32;

    // Load + transpose W: WT[k*129 + j] = W[j*128 + k] (conflict-free both ways)
    for (int idx = t; idx < D * D; idx += 256) {
        int j = idx >> 7;
        int k = idx & 127;
        WT[k * 129 + j] = W[idx];
    }

    const float4* X4 = (const float4*)X;
    for (int idx = t; idx < 32 * 32; idx += 256) {
        int row = idx >> 5;
        int kk = idx & 31;
        float4 v = make_float4(0.f, 0.f, 0.f, 0.f);
        if (R0 + row < n) v = X4[(size_t)(R0 + row) * 32 + kk];
        xs4[idx] = v;
    }
    __syncthreads();

    const int c = t & 127;
    const int rg = t >> 7;

    float acc[16];
#pragma unroll
    for (int i = 0; i < 16; i++) acc[i] = 0.f;

#pragma unroll 2
    for (int k4 = 0; k4 < 32; ++k4) {
        const int kb = k4 * 4;
        float w0 = WT[(kb + 0) * 129 + c];
        float w1 = WT[(kb + 1) * 129 + c];
        float w2 = WT[(kb + 2) * 129 + c];
        float w3 = WT[(kb + 3) * 129 + c];
#pragma unroll
        for (int i = 0; i < 16; i++) {
            float4 xv = xs4[(rg * 16 + i) * 32 + k4];  // warp-broadcast
            acc[i] = fmaf(xv.x, w0, acc[i]);
            acc[i] = fmaf(xv.y, w1, acc[i]);
            acc[i] = fmaf(xv.z, w2, acc[i]);
            acc[i] = fmaf(xv.w, w3, acc[i]);
        }
    }

#pragma unroll
    for (int i = 0; i < 16; i++) {
        int row = R0 + rg * 16 + i;
        if (row < n) g_h_half[(size_t)row * D + c] = __float2half_rn(acc[i]);
    }
}

// ---------------------------------------------------------------------------
// CSR build: zero counts -> histogram -> scan -> scatter
// ---------------------------------------------------------------------------
__global__ void zero_counts_kernel(int n) {
    int i = blockIdx.x * blockDim.x + threadIdx.x;
    if (i < n) g_count[i] = 0;
}

__global__ void hist_kernel(const int* __restrict__ rows, int GE) {
    int i = blockIdx.x * blockDim.x + threadIdx.x;
    if (i < GE) atomicAdd(&g_count[rows[i]], 1);  // no return use -> RED
}

// Single-block exclusive scan over g_count (n up to N_MAX), writes start+cursor.
__global__ void scan_kernel(int n) {
    __shared__ int ss[1024];
    const int t = threadIdx.x;
    const int chunk = (n + 1023) >> 10;
    const int lo = t * chunk;
    const int hi = min(lo + chunk, n);

    int s = 0;
    for (int i = lo; i < hi; i++) s += g_count[i];
    ss[t] = s;
    __syncthreads();

    // Kogge-Stone inclusive scan
    for (int off = 1; off < 1024; off <<= 1) {
        int v = (t >= off) ? ss[t - off] : 0;
        __syncthreads();
        ss[t] += v;
        __syncthreads();
    }

    int run = (t == 0) ? 0 : ss[t - 1];  // exclusive base
    for (int i = lo; i < hi; i++) {
        g_start[i] = run;
        g_cursor[i] = run;
        run += g_count[i];
    }
    if (lo < n && hi == n) g_start[n] = run;
}

__global__ void scatter_kernel(const int* __restrict__ rows,
                               const int* __restrict__ cols,
                               const float* __restrict__ vals,
                               const float* __restrict__ alpha,
                               int E, int GE) {
    const float ga0 = 1.f / (1.f + __expf(-__ldg(alpha + 0)));
    const float ga1 = 1.f / (1.f + __expf(-__ldg(alpha + 1)));
    const float ga2 = 1.f / (1.f + __expf(-__ldg(alpha + 2)));

    int e = blockIdx.x * blockDim.x + threadIdx.x;
    if (e >= GE) return;
    int r = rows[e];
    int c = cols[e];
    float v = vals[e];
    float gate = (e < E) ? ga0 : ((e < 2 * E) ? ga1 : ga2);
    int pos = atomicAdd(&g_cursor[r], 1);
    g_cv[pos] = make_int2(c, __float_as_int(v * gate));
}

// ---------------------------------------------------------------------------
// SPMM over CSR: warp per destination row, register accumulation, one store.
// Per edge: 2 SHFL broadcast + one 8B fp16 gather per lane + 4 FMA.
// ---------------------------------------------------------------------------
__global__ void spmm_csr_kernel(float* __restrict__ out, int n) {
    const int warp = (blockIdx.x * blockDim.x + threadIdx.x) >> 5;
    const int lane = threadIdx.x & 31;
    if (warp >= n) return;

    const int start = g_start[warp];
    const int end   = g_start[warp + 1];

    float ax = 0.f, ay = 0.f, az = 0.f, aw = 0.f;
    const __half* H = g_h_half;

    for (int base = start; base < end; base += 32) {
        int j = base + lane;
        int2 cv = make_int2(0, 0);
        if (j < end) cv = g_cv[j];
        const int m = min(32, end - base);
#pragma unroll 4
        for (int jj = 0; jj < m; jj++) {
            int   c = __shfl_sync(0xffffffffu, cv.x, jj);
            float v = __int_as_float(__shfl_sync(0xffffffffu, cv.y, jj));
            uint2 hp = *(const uint2*)(H + (size_t)c * D + lane * 4);
            float2 f01 = __half22float2(*(const __half2*)&hp.x);
            float2 f23 = __half22float2(*(const __half2*)&hp.y);
            ax = fmaf(v, f01.x, ax);
            ay = fmaf(v, f01.y, ay);
            az = fmaf(v, f23.x, az);
            aw = fmaf(v, f23.y, aw);
        }
    }

    ((float4*)(out + (size_t)warp * D))[lane] = make_float4(ax, ay, az, aw);
}

// ---------------------------------------------------------------------------
extern "C" void kernel_launch(void* const* d_in, const int* in_sizes, int n_in,
                              void* d_out, int out_size) {
    const float* X     = (const float*)d_in[0];
    const float* W     = (const float*)d_in[1];
    const float* alpha = (const float*)d_in[2];
    const int*   rows  = (const int*)d_in[3];
    const int*   cols  = (const int*)d_in[4];
    const float* vals  = (const float*)d_in[5];
    float* out = (float*)d_out;

    const int n  = in_sizes[0] / D;      // 50000
    const int G  = in_sizes[2];          // 3
    const int GE = in_sizes[3];          // 2400000
    const int E  = GE / G;               // 800000

    // GEMM (independent of CSR build)
    const int smem = (128 * 129 + 32 * 128) * 4;  // 82432 B
    cudaFuncSetAttribute(gemm_xwt_kernel,
                         cudaFuncAttributeMaxDynamicSharedMemorySize, smem);
    gemm_xwt_kernel<<<(n + 31) / 32, 256, smem>>>(X, W, n);

    // CSR build
    zero_counts_kernel<<<(n + 255) / 256, 256>>>(n);
    hist_kernel<<<(GE + 255) / 256, 256>>>(rows, GE);
    scan_kernel<<<1, 1024>>>(n);
    scatter_kernel<<<(GE + 255) / 256, 256>>>(rows, cols, vals, alpha, E, GE);

    // SPMM (warp per row)
    const int warps_per_block = 8;
    const int blocks = (n + warps_per_block - 1) / warps_per_block;
    spmm_csr_kernel<<<blocks, warps_per_block * 32>>>(out, n);
}

// round 3
// speedup vs baseline: 1.6575x; 1.3433x over previous
#include <cuda_runtime.h>
#include <cuda_fp16.h>

#define D 128
#define N_MAX 50000
#define E_MAX 2400000

// Scratch (static device arrays per harness rules)
__device__ __half g_h_half[(size_t)N_MAX * D];   // projected features, fp16 (12.8MB)
__device__ int2   g_cv[E_MAX];                   // CSR payload: (col, gate*val)
__device__ int    g_count[N_MAX];
__device__ int    g_start[N_MAX + 1];
__device__ int    g_cursor[N_MAX];
__device__ int    g_blocksum[256];

// ---------------------------------------------------------------------------
// Fused kernel: blocks [0, gemmBlocks) compute h = X @ W^T -> fp16,
// blocks [gemmBlocks, gridDim) build the row histogram concurrently.
// ---------------------------------------------------------------------------
__global__ void gemm_hist_kernel(const float* __restrict__ X,
                                 const float* __restrict__ W,
                                 const int* __restrict__ rows,
                                 int n, int GE, int gemmBlocks) {
    if (blockIdx.x >= gemmBlocks) {
        // ---- histogram part (vectorized, grid-stride) ----
        const int hb = blockIdx.x - gemmBlocks;
        const int nhb = gridDim.x - gemmBlocks;
        const int GE4 = GE >> 2;
        const int4* r4 = (const int4*)rows;
        for (int i = hb * blockDim.x + threadIdx.x; i < GE4;
             i += nhb * blockDim.x) {
            int4 r = r4[i];
            atomicAdd(&g_count[r.x], 1);
            atomicAdd(&g_count[r.y], 1);
            atomicAdd(&g_count[r.z], 1);
            atomicAdd(&g_count[r.w], 1);
        }
        // tail
        if (hb == 0) {
            for (int i = (GE4 << 2) + threadIdx.x; i < GE; i += blockDim.x)
                atomicAdd(&g_count[rows[i]], 1);
        }
        return;
    }

    // ---- gemm part ----
    extern __shared__ float sm[];
    float* WT = sm;                 // 128*129
    float* xs = sm + 128 * 129;     // 32*128
    float4* xs4 = (float4*)xs;

    const int t = threadIdx.x;
    const int R0 = blockIdx.x * 32;

    for (int idx = t; idx < D * D; idx += 256) {
        int j = idx >> 7;
        int k = idx & 127;
        WT[k * 129 + j] = W[idx];   // conflict-free store & load (pad 129)
    }

    const float4* X4 = (const float4*)X;
    for (int idx = t; idx < 32 * 32; idx += 256) {
        int row = idx >> 5;
        int kk = idx & 31;
        float4 v = make_float4(0.f, 0.f, 0.f, 0.f);
        if (R0 + row < n) v = X4[(size_t)(R0 + row) * 32 + kk];
        xs4[idx] = v;
    }
    __syncthreads();

    const int c = t & 127;
    const int rg = t >> 7;

    float acc[16];
#pragma unroll
    for (int i = 0; i < 16; i++) acc[i] = 0.f;

#pragma unroll 2
    for (int k4 = 0; k4 < 32; ++k4) {
        const int kb = k4 * 4;
        float w0 = WT[(kb + 0) * 129 + c];
        float w1 = WT[(kb + 1) * 129 + c];
        float w2 = WT[(kb + 2) * 129 + c];
        float w3 = WT[(kb + 3) * 129 + c];
#pragma unroll
        for (int i = 0; i < 16; i++) {
            float4 xv = xs4[(rg * 16 + i) * 32 + k4];  // warp-broadcast
            acc[i] = fmaf(xv.x, w0, acc[i]);
            acc[i] = fmaf(xv.y, w1, acc[i]);
            acc[i] = fmaf(xv.z, w2, acc[i]);
            acc[i] = fmaf(xv.w, w3, acc[i]);
        }
    }

#pragma unroll
    for (int i = 0; i < 16; i++) {
        int row = R0 + rg * 16 + i;
        if (row < n) g_h_half[(size_t)row * D + c] = __float2half_rn(acc[i]);
    }
}

// ---------------------------------------------------------------------------
// Parallel scan, 3 phases. Block = 256 threads handling 1024 counts (int4).
// ---------------------------------------------------------------------------
__global__ void scan_phase1(int n) {
    const int n4 = n >> 2;
    const int i4 = blockIdx.x * 256 + threadIdx.x;
    const int4* c4 = (const int4*)g_count;
    int s = 0;
    if (i4 < n4) {
        int4 c = c4[i4];
        s = c.x + c.y + c.z + c.w;
    } else {
        for (int i = (n4 << 2) + (i4 - n4); i < n && i4 >= n4; ) { s = g_count[i]; break; }
    }
    // warp reduce
    for (int off = 16; off; off >>= 1) s += __shfl_down_sync(0xffffffffu, s, off);
    __shared__ int ws[8];
    const int lane = threadIdx.x & 31, w = threadIdx.x >> 5;
    if (lane == 0) ws[w] = s;
    __syncthreads();
    if (w == 0) {
        int v = (lane < 8) ? ws[lane] : 0;
        for (int off = 4; off; off >>= 1) v += __shfl_down_sync(0xffffffffu, v, off);
        if (lane == 0) g_blocksum[blockIdx.x] = v;
    }
}

__global__ void scan_phase2(int nblocks, int n) {
    // single block of 256; exclusive scan of nblocks (<=256) block sums
    __shared__ int ss[256];
    const int t = threadIdx.x;
    int v = (t < nblocks) ? g_blocksum[t] : 0;
    ss[t] = v;
    __syncthreads();
    for (int off = 1; off < 256; off <<= 1) {
        int u = (t >= off) ? ss[t - off] : 0;
        __syncthreads();
        ss[t] += u;
        __syncthreads();
    }
    if (t < nblocks) g_blocksum[t] = (t == 0) ? 0 : ss[t - 1];
    if (t == 0) g_start[n] = ss[255];
}

__global__ void scan_phase3(int n) {
    const int n4 = n >> 2;
    const int i4 = blockIdx.x * 256 + threadIdx.x;
    const int4* c4 = (const int4*)g_count;
    int4 c = make_int4(0, 0, 0, 0);
    if (i4 < n4) c = c4[i4];
    int s = c.x + c.y + c.z + c.w;

    // warp inclusive scan
    int incl = s;
    const int lane = threadIdx.x & 31, w = threadIdx.x >> 5;
    for (int off = 1; off < 32; off <<= 1) {
        int u = __shfl_up_sync(0xffffffffu, incl, off);
        if (lane >= off) incl += u;
    }
    __shared__ int ws[8];
    if (lane == 31) ws[w] = incl;
    __syncthreads();
    __shared__ int wbase[8];
    if (threadIdx.x < 8) {
        int v = ws[threadIdx.x];
        int e = 0;
        for (int k = 0; k < 8; k++) {
            int u = __shfl_sync(0xffu, v, k, 8);
            if (k < threadIdx.x) e += u;
        }
        wbase[threadIdx.x] = e;
    }
    __syncthreads();

    int base = g_blocksum[blockIdx.x] + wbase[w] + (incl - s);  // exclusive prefix
    if (i4 < n4) {
        int i = i4 << 2;
        int p0 = base, p1 = base + c.x, p2 = p1 + c.y, p3 = p2 + c.z;
        ((int4*)g_start)[i4] = make_int4(p0, p1, p2, p3);
        ((int4*)g_cursor)[i4] = make_int4(p0, p1, p2, p3);
    }
}

// ---------------------------------------------------------------------------
// Scatter edges into CSR slots (vectorized 4 edges/thread)
// ---------------------------------------------------------------------------
__global__ void scatter_kernel(const int* __restrict__ rows,
                               const int* __restrict__ cols,
                               const float* __restrict__ vals,
                               const float* __restrict__ alpha,
                               int E, int GE) {
    const float ga0 = 1.f / (1.f + __expf(-__ldg(alpha + 0)));
    const float ga1 = 1.f / (1.f + __expf(-__ldg(alpha + 1)));
    const float ga2 = 1.f / (1.f + __expf(-__ldg(alpha + 2)));

    const int GE4 = GE >> 2;
    int i4 = blockIdx.x * blockDim.x + threadIdx.x;
    if (i4 < GE4) {
        int4 r = ((const int4*)rows)[i4];
        int4 c = ((const int4*)cols)[i4];
        float4 v = ((const float4*)vals)[i4];
        int e = i4 << 2;
#pragma unroll
        for (int k = 0; k < 4; k++) {
            int rr = (&r.x)[k];
            int cc = (&c.x)[k];
            float vv = (&v.x)[k];
            int ee = e + k;
            float gate = (ee < E) ? ga0 : ((ee < 2 * E) ? ga1 : ga2);
            int pos = atomicAdd(&g_cursor[rr], 1);
            g_cv[pos] = make_int2(cc, __float_as_int(vv * gate));
        }
    } else {
        for (int e = (GE4 << 2) + (i4 - GE4); e < GE && i4 >= GE4; ) {
            int rr = rows[e];
            float gate = (e < E) ? ga0 : ((e < 2 * E) ? ga1 : ga2);
            int pos = atomicAdd(&g_cursor[rr], 1);
            g_cv[pos] = make_int2(cols[e], __float_as_int(vals[e] * gate));
            break;
        }
    }
}

// ---------------------------------------------------------------------------
// SPMM over CSR: warp per destination row, register accum, one 512B store.
// ---------------------------------------------------------------------------
__global__ void spmm_csr_kernel(float* __restrict__ out, int n) {
    const int warp = (blockIdx.x * blockDim.x + threadIdx.x) >> 5;
    const int lane = threadIdx.x & 31;
    if (warp >= n) return;

    const int start = g_start[warp];
    const int end   = g_start[warp + 1];

    float ax = 0.f, ay = 0.f, az = 0.f, aw = 0.f;
    const __half* H = g_h_half;

    for (int base = start; base < end; base += 32) {
        int j = base + lane;
        int2 cv = make_int2(0, 0);
        if (j < end) cv = g_cv[j];
        const int m = min(32, end - base);
#pragma unroll 4
        for (int jj = 0; jj < m; jj++) {
            int   c = __shfl_sync(0xffffffffu, cv.x, jj);
            float v = __int_as_float(__shfl_sync(0xffffffffu, cv.y, jj));
            uint2 hp = *(const uint2*)(H + (size_t)c * D + lane * 4);
            float2 f01 = __half22float2(*(const __half2*)&hp.x);
            float2 f23 = __half22float2(*(const __half2*)&hp.y);
            ax = fmaf(v, f01.x, ax);
            ay = fmaf(v, f01.y, ay);
            az = fmaf(v, f23.x, az);
            aw = fmaf(v, f23.y, aw);
        }
    }

    ((float4*)(out + (size_t)warp * D))[lane] = make_float4(ax, ay, az, aw);
}

// ---------------------------------------------------------------------------
extern "C" void kernel_launch(void* const* d_in, const int* in_sizes, int n_in,
                              void* d_out, int out_size) {
    const float* X     = (const float*)d_in[0];
    const float* W     = (const float*)d_in[1];
    const float* alpha = (const float*)d_in[2];
    const int*   rows  = (const int*)d_in[3];
    const int*   cols  = (const int*)d_in[4];
    const float* vals  = (const float*)d_in[5];
    float* out = (float*)d_out;

    const int n  = in_sizes[0] / D;      // 50000
    const int G  = in_sizes[2];          // 3
    const int GE = in_sizes[3];          // 2400000
    const int E  = GE / G;               // 800000

    // zero counts (memset node)
    void* countPtr = nullptr;
    cudaGetSymbolAddress(&countPtr, g_count);
    cudaMemsetAsync(countPtr, 0, (size_t)n * sizeof(int), 0);

    // fused gemm + histogram
    const int gemmBlocks = (n + 31) / 32;
    const int histBlocks = 128;
    const int smem = (128 * 129 + 32 * 128) * 4;  // 82432 B
    cudaFuncSetAttribute(gemm_hist_kernel,
                         cudaFuncAttributeMaxDynamicSharedMemorySize, smem);
    gemm_hist_kernel<<<gemmBlocks + histBlocks, 256, smem>>>(X, W, rows, n, GE, gemmBlocks);

    // parallel scan
    const int scanBlocks = (n + 1023) / 1024;     // 49 for n=50000
    scan_phase1<<<scanBlocks, 256>>>(n);
    scan_phase2<<<1, 256>>>(scanBlocks, n);
    scan_phase3<<<scanBlocks, 256>>>(n);

    // scatter
    scatter_kernel<<<((GE >> 2) + 255) / 256 + 1, 256>>>(rows, cols, vals, alpha, E, GE);

    // SPMM (warp per row)
    const int warps_per_block = 8;
    const int blocks = (n + warps_per_block - 1) / warps_per_block;
    spmm_csr_kernel<<<blocks, warps_per_block * 32>>>(out, n);
}

// round 8
// speedup vs baseline: 2.5367x; 1.5305x over previous
#include <cuda_runtime.h>
#include <cuda_fp16.h>
#include <cstdint>

typedef unsigned int u32;

#define D 128
#define LDW 136   // padded smem row length (halves): 272B stride -> conflict-free LDSM
#define N_MAX 50000
#define E_MAX 2400000

// Scratch (static device arrays per harness rules)
__device__ __half g_h_half[(size_t)N_MAX * D];   // projected features, fp16
__device__ int2   g_cv[E_MAX];                   // CSR payload: (col, gate*val)
__device__ int    g_count[N_MAX];
__device__ int    g_start[N_MAX + 1];
__device__ int    g_cursor[N_MAX];
__device__ int    g_blocksum[256];

__device__ __forceinline__ u32 smem_u32(const void* p) {
    return (u32)__cvta_generic_to_shared(p);
}

__device__ __forceinline__ void ldsm_x4(u32& r0, u32& r1, u32& r2, u32& r3,
                                        u32 addr) {
    asm volatile("ldmatrix.sync.aligned.m8n8.x4.shared.b16 {%0,%1,%2,%3}, [%4];"
                 : "=r"(r0), "=r"(r1), "=r"(r2), "=r"(r3)
                 : "r"(addr));
}

__device__ __forceinline__ void mma_16816(float* c,
                                          u32 a0, u32 a1, u32 a2, u32 a3,
                                          u32 b0, u32 b1) {
    asm volatile("mma.sync.aligned.m16n8k16.row.col.f32.f16.f16.f32 "
                 "{%0,%1,%2,%3}, {%4,%5,%6,%7}, {%8,%9}, {%0,%1,%2,%3};"
                 : "+f"(c[0]), "+f"(c[1]), "+f"(c[2]), "+f"(c[3])
                 : "r"(a0), "r"(a1), "r"(a2), "r"(a3), "r"(b0), "r"(b1));
}

// ---------------------------------------------------------------------------
// Fused kernel: blocks [0, gemmBlocks) compute h = X @ W^T via fp16 mma.sync
// (fp32 accumulate), blocks [gemmBlocks, grid) build the row histogram.
// ---------------------------------------------------------------------------
__global__ void __launch_bounds__(256)
gemm_hist_kernel(const float* __restrict__ X,
                 const float* __restrict__ W,
                 const int* __restrict__ rows,
                 int n, int GE, int gemmBlocks) {
    if (blockIdx.x >= gemmBlocks) {
        // ---- histogram (vectorized, grid-stride) ----
        const int hb = blockIdx.x - gemmBlocks;
        const int nhb = gridDim.x - gemmBlocks;
        const int GE4 = GE >> 2;
        const int4* r4 = (const int4*)rows;
        for (int i = hb * blockDim.x + threadIdx.x; i < GE4;
             i += nhb * blockDim.x) {
            int4 r = r4[i];
            atomicAdd(&g_count[r.x], 1);
            atomicAdd(&g_count[r.y], 1);
            atomicAdd(&g_count[r.z], 1);
            atomicAdd(&g_count[r.w], 1);
        }
        if (hb == 0) {
            for (int i = (GE4 << 2) + threadIdx.x; i < GE; i += blockDim.x)
                atomicAdd(&g_count[rows[i]], 1);
        }
        return;
    }

    // ---- GEMM via mma.sync.m16n8k16 (fp16 in, fp32 acc) ----
    extern __shared__ __half sh[];
    __half* Xs = sh;                 // [128][LDW]
    __half* Ws = sh + 128 * LDW;     // [128][LDW]

    const int t = threadIdx.x;
    const int R0 = blockIdx.x * 128;

    // Load W [128][128] f32 -> fp16 smem (row-major; rows of W == cols of B)
    const float4* W4 = (const float4*)W;
    for (int idx = t; idx < 128 * 32; idx += 256) {
        int r = idx >> 5, c4 = idx & 31;
        float4 v = W4[idx];
        __half2* dst = (__half2*)(Ws + r * LDW + c4 * 4);
        dst[0] = __floats2half2_rn(v.x, v.y);
        dst[1] = __floats2half2_rn(v.z, v.w);
    }
    // Load X tile (128 rows) f32 -> fp16 smem
    const float4* X4 = (const float4*)X;
    for (int idx = t; idx < 128 * 32; idx += 256) {
        int r = idx >> 5, c4 = idx & 31;
        int gr = R0 + r;
        float4 v = make_float4(0.f, 0.f, 0.f, 0.f);
        if (gr < n) v = X4[(size_t)gr * 32 + c4];
        __half2* dst = (__half2*)(Xs + r * LDW + c4 * 4);
        dst[0] = __floats2half2_rn(v.x, v.y);
        dst[1] = __floats2half2_rn(v.z, v.w);
    }
    __syncthreads();

    const int warp = t >> 5;
    const int lane = t & 31;
    const int m0 = warp * 16;

    float acc[16][4];
#pragma unroll
    for (int i = 0; i < 16; i++) {
#pragma unroll
        for (int j = 0; j < 4; j++) acc[i][j] = 0.f;
    }

    // A fragment: row = m0 + (lane&15), col = k0 + (lane>>4)*8
    const u32 a_base =
        smem_u32(Xs + (m0 + (lane & 15)) * LDW + ((lane >> 4) << 3));
    // B fragment (x4 = n16 x k16): row = nb + ((lane>>4)<<3) + (lane&7),
    //                              col = k0 + (((lane>>3)&1)<<3)
    const int b_row_off = ((lane >> 4) << 3) + (lane & 7);
    const int b_col_off = ((lane >> 3) & 1) << 3;

#pragma unroll
    for (int k0 = 0; k0 < 128; k0 += 16) {
        u32 a0, a1, a2, a3;
        ldsm_x4(a0, a1, a2, a3, a_base + (u32)(k0 * 2));
#pragma unroll
        for (int nt = 0; nt < 8; nt++) {
            u32 b0, b1, b2, b3;
            u32 baddr =
                smem_u32(Ws + (nt * 16 + b_row_off) * LDW + k0 + b_col_off);
            ldsm_x4(b0, b1, b2, b3, baddr);
            mma_16816(&acc[nt * 2][0],     a0, a1, a2, a3, b0, b1);
            mma_16816(&acc[nt * 2 + 1][0], a0, a1, a2, a3, b2, b3);
        }
    }

    // Store: c0,c1 at (row = lane/4, cols 2*(lane%4)+{0,1}); c2,c3 at row+8
    const int rA = R0 + m0 + (lane >> 2);
    const int rB = rA + 8;
    const int ccol = (lane & 3) * 2;
    if (rA < n) {
#pragma unroll
        for (int nt = 0; nt < 16; nt++) {
            *(__half2*)&g_h_half[(size_t)rA * D + nt * 8 + ccol] =
                __floats2half2_rn(acc[nt][0], acc[nt][1]);
        }
    }
    if (rB < n) {
#pragma unroll
        for (int nt = 0; nt < 16; nt++) {
            *(__half2*)&g_h_half[(size_t)rB * D + nt * 8 + ccol] =
                __floats2half2_rn(acc[nt][2], acc[nt][3]);
        }
    }
}

// ---------------------------------------------------------------------------
// Parallel scan, 3 phases.
// ---------------------------------------------------------------------------
__global__ void scan_phase1(int n) {
    const int n4 = n >> 2;
    const int i4 = blockIdx.x * 256 + threadIdx.x;
    const int4* c4 = (const int4*)g_count;
    int s = 0;
    if (i4 < n4) {
        int4 c = c4[i4];
        s = c.x + c.y + c.z + c.w;
    } else {
        for (int i = i4 << 2; i < n; i++) s += g_count[i];
    }
    for (int off = 16; off; off >>= 1) s += __shfl_down_sync(0xffffffffu, s, off);
    __shared__ int ws[8];
    const int lane = threadIdx.x & 31;
    const int w = threadIdx.x >> 5;
    if (lane == 0) ws[w] = s;
    __syncthreads();
    if (w == 0) {
        int v = (lane < 8) ? ws[lane] : 0;
        for (int off = 4; off; off >>= 1) v += __shfl_down_sync(0xffffffffu, v, off);
        if (lane == 0) g_blocksum[blockIdx.x] = v;
    }
}

__global__ void scan_phase2(int nblocks, int n) {
    __shared__ int ss[256];
    const int t = threadIdx.x;
    int v = (t < nblocks) ? g_blocksum[t] : 0;
    ss[t] = v;
    __syncthreads();
    for (int off = 1; off < 256; off <<= 1) {
        int u = (t >= off) ? ss[t - off] : 0;
        __syncthreads();
        ss[t] += u;
        __syncthreads();
    }
    if (t < nblocks) g_blocksum[t] = (t == 0) ? 0 : ss[t - 1];
    if (t == 0) g_start[n] = ss[255];
}

__global__ void scan_phase3(int n) {
    const int n4 = n >> 2;
    const int i4 = blockIdx.x * 256 + threadIdx.x;
    const int4* c4 = (const int4*)g_count;
    int4 c = make_int4(0, 0, 0, 0);
    bool vec = (i4 < n4);
    if (vec) {
        c = c4[i4];
    } else {
        int i = i4 << 2;
        if (i + 0 < n) c.x = g_count[i + 0];
        if (i + 1 < n) c.y = g_count[i + 1];
        if (i + 2 < n) c.z = g_count[i + 2];
        if (i + 3 < n) c.w = g_count[i + 3];
    }
    int s = c.x + c.y + c.z + c.w;

    int incl = s;
    const int lane = threadIdx.x & 31;
    const int w = threadIdx.x >> 5;
    for (int off = 1; off < 32; off <<= 1) {
        int u = __shfl_up_sync(0xffffffffu, incl, off);
        if (lane >= off) incl += u;
    }
    __shared__ int ws[8];
    if (lane == 31) ws[w] = incl;
    __syncthreads();
    __shared__ int wbase[8];
    if (threadIdx.x < 8) {
        int v = ws[threadIdx.x];
        int e = 0;
        for (int k = 0; k < 8; k++) {
            int u = __shfl_sync(0xffu, v, k, 8);
            if (k < threadIdx.x) e += u;
        }
        wbase[threadIdx.x] = e;
    }
    __syncthreads();

    int base = g_blocksum[blockIdx.x] + wbase[w] + (incl - s);
    int p0 = base;
    int p1 = base + c.x;
    int p2 = p1 + c.y;
    int p3 = p2 + c.z;
    if (vec) {
        ((int4*)g_start)[i4] = make_int4(p0, p1, p2, p3);
        ((int4*)g_cursor)[i4] = make_int4(p0, p1, p2, p3);
    } else {
        int i = i4 << 2;
        int ps[4];
        ps[0] = p0; ps[1] = p1; ps[2] = p2; ps[3] = p3;
        for (int k = 0; k < 4 && i + k < n; k++) {
            g_start[i + k] = ps[k];
            g_cursor[i + k] = ps[k];
        }
    }
}

// ---------------------------------------------------------------------------
// Scatter edges into CSR slots (4 edges/thread)
// ---------------------------------------------------------------------------
__global__ void scatter_kernel(const int* __restrict__ rows,
                               const int* __restrict__ cols,
                               const float* __restrict__ vals,
                               const float* __restrict__ alpha,
                               int E, int GE) {
    const float ga0 = 1.f / (1.f + __expf(-__ldg(alpha + 0)));
    const float ga1 = 1.f / (1.f + __expf(-__ldg(alpha + 1)));
    const float ga2 = 1.f / (1.f + __expf(-__ldg(alpha + 2)));

    const int GE4 = GE >> 2;
    int i4 = blockIdx.x * blockDim.x + threadIdx.x;
    if (i4 < GE4) {
        int4 r = ((const int4*)rows)[i4];
        int4 c = ((const int4*)cols)[i4];
        float4 v = ((const float4*)vals)[i4];
        int e = i4 << 2;
#pragma unroll
        for (int k = 0; k < 4; k++) {
            int rr = (&r.x)[k];
            int cc = (&c.x)[k];
            float vv = (&v.x)[k];
            int ee = e + k;
            float gate = (ee < E) ? ga0 : ((ee < 2 * E) ? ga1 : ga2);
            int pos = atomicAdd(&g_cursor[rr], 1);
            g_cv[pos] = make_int2(cc, __float_as_int(vv * gate));
        }
    } else {
        for (int e = i4 << 2; e < GE; e++) {
            int rr = rows[e];
            float gate = (e < E) ? ga0 : ((e < 2 * E) ? ga1 : ga2);
            int pos = atomicAdd(&g_cursor[rr], 1);
            g_cv[pos] = make_int2(cols[e], __float_as_int(vals[e] * gate));
        }
    }
}

// ---------------------------------------------------------------------------
// SPMM over CSR: warp per destination row, register accum, one 512B store.
// ---------------------------------------------------------------------------
__global__ void spmm_csr_kernel(float* __restrict__ out, int n) {
    const int warp = (blockIdx.x * blockDim.x + threadIdx.x) >> 5;
    const int lane = threadIdx.x & 31;
    if (warp >= n) return;

    const int start = g_start[warp];
    const int end   = g_start[warp + 1];

    float ax = 0.f, ay = 0.f, az = 0.f, aw = 0.f;
    const __half* H = g_h_half;

    for (int base = start; base < end; base += 32) {
        int j = base + lane;
        int2 cv = make_int2(0, 0);
        if (j < end) cv = g_cv[j];
        const int m = min(32, end - base);
#pragma unroll 4
        for (int jj = 0; jj < m; jj++) {
            int   c = __shfl_sync(0xffffffffu, cv.x, jj);
            float v = __int_as_float(__shfl_sync(0xffffffffu, cv.y, jj));
            uint2 hp = *(const uint2*)(H + (size_t)c * D + lane * 4);
            float2 f01 = __half22float2(*(const __half2*)&hp.x);
            float2 f23 = __half22float2(*(const __half2*)&hp.y);
            ax = fmaf(v, f01.x, ax);
            ay = fmaf(v, f01.y, ay);
            az = fmaf(v, f23.x, az);
            aw = fmaf(v, f23.y, aw);
        }
    }

    ((float4*)(out + (size_t)warp * D))[lane] = make_float4(ax, ay, az, aw);
}

// ---------------------------------------------------------------------------
extern "C" void kernel_launch(void* const* d_in, const int* in_sizes, int n_in,
                              void* d_out, int out_size) {
    const float* X     = (const float*)d_in[0];
    const float* W     = (const float*)d_in[1];
    const float* alpha = (const float*)d_in[2];
    const int*   rows  = (const int*)d_in[3];
    const int*   cols  = (const int*)d_in[4];
    const float* vals  = (const float*)d_in[5];
    float* out = (float*)d_out;

    const int n  = in_sizes[0] / D;      // 50000
    const int G  = in_sizes[2];          // 3
    const int GE = in_sizes[3];          // 2400000
    const int E  = GE / G;               // 800000

    void* countPtr = 0;
    cudaGetSymbolAddress(&countPtr, g_count);
    cudaMemsetAsync(countPtr, 0, (size_t)n * sizeof(int), 0);

    // fused tensor-core gemm + histogram
    const int gemmBlocks = (n + 127) / 128;       // 391
    const int histBlocks = 148;
    const int smem = 2 * 128 * LDW * (int)sizeof(__half);  // 69632 B
    cudaFuncSetAttribute(gemm_hist_kernel,
                         cudaFuncAttributeMaxDynamicSharedMemorySize, smem);
    gemm_hist_kernel<<<gemmBlocks + histBlocks, 256, smem>>>(X, W, rows, n, GE, gemmBlocks);

    // parallel scan
    const int scanBlocks = (n + 1023) / 1024;     // 49
    scan_phase1<<<scanBlocks, 256>>>(n);
    scan_phase2<<<1, 256>>>(scanBlocks, n);
    scan_phase3<<<scanBlocks, 256>>>(n);

    // scatter
    scatter_kernel<<<((GE >> 2) + 255) / 256 + 1, 256>>>(rows, cols, vals, alpha, E, GE);

    // SPMM (warp per row)
    const int warps_per_block = 8;
    const int blocks = (n + warps_per_block - 1) / warps_per_block;
    spmm_csr_kernel<<<blocks, warps_per_block * 32>>>(out, n);
}